// round 15
// baseline (speedup 1.0000x reference)
#include <cuda_runtime.h>
#include <math.h>

// Problem constants
#define NB 128       // batch
#define GRID 128
#define THREADS 512
#define SPLITK 16    // split-K for fc1 (kc=64) and fc2 (kc=128)

// ---------------- device scratch (no allocations allowed) ----------------
__device__ float d_cs[NB * 64 * 512];          // chart states, slot-addressed
__device__ float d_C0[NB * 64 * 512];          // init GEMM output
__device__ float d_part1[SPLITK * NB * 2048];  // fc1 split-K partials
__device__ float d_part2[SPLITK * NB * 2048];  // fc2 split-K partials
__device__ float d_h[NB * 2048];               // fc1 activations
__device__ float d_xcat[NB * 1024];            // [l, r] concat for selected pairs
__device__ float d_logits[NB * 64];            // cached raw pair logits
__device__ int   d_idx[NB * 64];               // active slot list per row
__device__ int   d_slotL[NB];
__device__ int   d_flag[NB];
__device__ int   d_prevk[NB];
// dataflow counters (generation-indexed, monotone within a launch)
__device__ unsigned int c_sel = 0;             // select completions (128/iter)
__device__ unsigned int c_grp[8] = {};         // fc1 group arrivals (16/iter each)
__device__ unsigned int c_red[8] = {};         // h-slice reduce completions
__device__ unsigned int c_fc2 = 0;             // fc2 job completions (128/iter)
__device__ unsigned int g_cnt = 0;             // classic grid barrier
__device__ unsigned int g_gen = 0;

struct GemmS { float As[2][16][128]; float Bs[2][16][256]; };   // 48 KB
struct SelS  { float fs[16][128]; float sv[512]; float red[512];
               float lg[64]; unsigned long long wmax[16]; int shk[4]; };
union SmemU  { GemmS g; SelS s; };

__device__ __forceinline__ float gelu_f(float x) {
    float x3 = x * x * x;
    return 0.5f * x * (1.0f + tanhf(0.7978845608028654f * (x + 0.044715f * x3)));
}
__device__ __forceinline__ float sigm_f(float x) {
    return 1.0f / (1.0f + expf(-x));
}

// ---------------- sync primitives ----------------
__device__ __forceinline__ void gsync() {
    __syncthreads();
    if (threadIdx.x == 0) {
        __threadfence();
        unsigned int g = *(volatile unsigned int*)&g_gen;
        if (atomicAdd(&g_cnt, 1u) == GRID - 1u) {
            g_cnt = 0u;
            __threadfence();
            *(volatile unsigned int*)&g_gen = g + 1u;
        } else {
            while (*(volatile unsigned int*)&g_gen == g) __nanosleep(32);
        }
        __threadfence();
    }
    __syncthreads();
}
__device__ __forceinline__ void arrive_cnt(unsigned int* c) {
    __threadfence();
    __syncthreads();
    if (threadIdx.x == 0) atomicAdd(c, 1u);
}
__device__ __forceinline__ void wait_cnt(unsigned int* c, unsigned int tgt) {
    if (threadIdx.x == 0) {
        while (*(volatile unsigned int*)c < tgt) __nanosleep(64);
        __threadfence();
    }
    __syncthreads();
}

// ---------------- 128x256 GEMM tile, 512 threads, double-buffered f32x2 ----------------
// A: (.)xK row-major, B: KxN row-major. C[m0:m0+128, n0:n0+256] over K-range
// [k0,k0+kc) into Co (leading dim N). Per-output accumulation order identical
// to the previous 128x128 version -> bit-identical results.
__device__ __forceinline__ void gemm_tile(
    const float* __restrict__ A, const float* __restrict__ B, float* __restrict__ Co,
    int N, int K, int m0, int n0, int k0, int kc, GemmS* sm)
{
    const int tid = threadIdx.x;
    const int tx = tid & 31;        // 32 col-groups of 8
    const int ty = tid >> 5;        // 16 row-groups of 8
    const int nk = kc >> 4;

    unsigned long long accp[8][4];
#pragma unroll
    for (int i = 0; i < 8; i++)
#pragma unroll
        for (int j = 0; j < 4; j++) accp[i][j] = 0ull;

    const int arow = tid >> 2;           // 0..127
    const int ac4  = (tid & 3) << 2;     // 0,4,8,12
    const int brow = tid >> 6;           // 0..7
    const int bc4  = (tid & 63) << 2;    // 0..252

    const float* Ap = A + (size_t)(m0 + arow) * K + k0 + ac4;
    const float* Bp = B + (size_t)(k0 + brow) * N + n0 + bc4;

    float4 ta  = *(const float4*)(Ap);
    float4 tb0 = *(const float4*)(Bp);
    float4 tb1 = *(const float4*)(Bp + (size_t)8 * N);
    sm->As[0][ac4 + 0][arow] = ta.x; sm->As[0][ac4 + 1][arow] = ta.y;
    sm->As[0][ac4 + 2][arow] = ta.z; sm->As[0][ac4 + 3][arow] = ta.w;
    *(float4*)&sm->Bs[0][brow][bc4]     = tb0;
    *(float4*)&sm->Bs[0][brow + 8][bc4] = tb1;
    __syncthreads();

    int buf = 0;
    for (int t = 0; t < nk; t++) {
        if (t + 1 < nk) {
            const float* Apn = Ap + (t + 1) * 16;
            const float* Bpn = Bp + (size_t)(t + 1) * 16 * N;
            ta  = *(const float4*)(Apn);
            tb0 = *(const float4*)(Bpn);
            tb1 = *(const float4*)(Bpn + (size_t)8 * N);
        }
#pragma unroll
        for (int kk = 0; kk < 16; kk++) {
            float av[8];
            unsigned long long avp[8], bvp[4];
            *(float4*)(av)     = *(const float4*)&sm->As[buf][kk][ty * 8];
            *(float4*)(av + 4) = *(const float4*)&sm->As[buf][kk][ty * 8 + 4];
            *(ulonglong2*)(bvp + 0) = *(const ulonglong2*)&sm->Bs[buf][kk][tx * 8 + 0];
            *(ulonglong2*)(bvp + 2) = *(const ulonglong2*)&sm->Bs[buf][kk][tx * 8 + 4];
#pragma unroll
            for (int i = 0; i < 8; i++)
                asm("mov.b64 %0, {%1, %1};" : "=l"(avp[i]) : "f"(av[i]));
#pragma unroll
            for (int i = 0; i < 8; i++)
#pragma unroll
                for (int j = 0; j < 4; j++)
                    asm("fma.rn.f32x2 %0, %1, %2, %0;"
                        : "+l"(accp[i][j]) : "l"(avp[i]), "l"(bvp[j]));
        }
        if (t + 1 < nk) {
            int nb = buf ^ 1;
            sm->As[nb][ac4 + 0][arow] = ta.x; sm->As[nb][ac4 + 1][arow] = ta.y;
            sm->As[nb][ac4 + 2][arow] = ta.z; sm->As[nb][ac4 + 3][arow] = ta.w;
            *(float4*)&sm->Bs[nb][brow][bc4]     = tb0;
            *(float4*)&sm->Bs[nb][brow + 8][bc4] = tb1;
            __syncthreads();
            buf = nb;
        }
    }

#pragma unroll
    for (int i = 0; i < 8; i++) {
        ulonglong2 v0 = make_ulonglong2(accp[i][0], accp[i][1]);
        ulonglong2 v1 = make_ulonglong2(accp[i][2], accp[i][3]);
        *(ulonglong2*)(Co + (size_t)(m0 + ty * 8 + i) * N + n0 + tx * 8)     = v0;
        *(ulonglong2*)(Co + (size_t)(m0 + ty * 8 + i) * N + n0 + tx * 8 + 4) = v1;
    }
}

// ---------------- fc2 split-K reduce + gates + LayerNorm into cs[sL] ----------------
__device__ void gate_ln(int n, const float* __restrict__ b2, const float* __restrict__ g,
                        const float* __restrict__ beta, SelS* sm)
{
    int tid = threadIdx.x;    // 512: one d per thread
    float* sv = sm->sv; float* red = sm->red;
    const float* base = d_part2 + (size_t)n * 2048;
    {
        int d = tid;
        float c0 = 0.f, c1 = 0.f, c2 = 0.f, c3 = 0.f;
#pragma unroll
        for (int z = 0; z < SPLITK; z++) {
            const float* pp = base + (size_t)z * (NB * 2048);
            c0 += pp[d]; c1 += pp[512 + d]; c2 += pp[1024 + d]; c3 += pp[1536 + d];
        }
        c0 += b2[d]; c1 += b2[512 + d]; c2 += b2[1024 + d]; c3 += b2[1536 + d];
        float l = d_xcat[(size_t)n * 1024 + d];
        float r = d_xcat[(size_t)n * 1024 + 512 + d];
        sv[d] = sigm_f(c0) * l + sigm_f(c1) * r + sigm_f(c2) * c3;
    }
    __syncthreads();
    red[tid] = sv[tid]; __syncthreads();
    for (int off = 256; off > 0; off >>= 1) {
        if (tid < off) red[tid] += red[tid + off];
        __syncthreads();
    }
    float mean = red[0] * (1.0f / 512.0f);
    __syncthreads();
    float d0 = sv[tid] - mean;
    red[tid] = d0 * d0; __syncthreads();
    for (int off = 256; off > 0; off >>= 1) {
        if (tid < off) red[tid] += red[tid + off];
        __syncthreads();
    }
    float inv = 1.0f / sqrtf(red[0] * (1.0f / 512.0f) + 1e-5f);
    float* dst = d_cs + (size_t)(n * 64 + d_slotL[n]) * 512;
    dst[tid] = (sv[tid] - mean) * inv * g[tid] + beta[tid];
    __syncthreads();
}

// ---------------- pair scorer (one warp per pair; weights from L2) ----------------
__device__ __forceinline__ void score_pair_g(
    int n, int j, int lane,
    const float* __restrict__ Wd1, const float* __restrict__ Wd2,
    const float* __restrict__ bd1, float bd2v, float* fsrow, float* lg)
{
    int a  = d_idx[n * 64 + j];
    int bs = d_idx[n * 64 + j + 1];
    const float* lrow = d_cs + (size_t)(n * 64 + a) * 512;
    const float* rrow = d_cs + (size_t)(n * 64 + bs) * 512;
    for (int t = lane; t < 128; t += 32)
        fsrow[t] = (t < 64) ? lrow[t] : rrow[t - 64];
    __syncwarp();
    float acc0 = 0.0f, acc1 = 0.0f;
#pragma unroll 8
    for (int k = 0; k < 128; k++) {
        float f = fsrow[k];
        acc0 = fmaf(f, Wd1[k * 64 + lane], acc0);
        acc1 = fmaf(f, Wd1[k * 64 + lane + 32], acc1);
    }
    float h0 = gelu_f(acc0 + bd1[lane]);
    float h1 = gelu_f(acc1 + bd1[lane + 32]);
    float part = h0 * Wd2[lane] + h1 * Wd2[lane + 32];
#pragma unroll
    for (int off = 16; off > 0; off >>= 1)
        part += __shfl_xor_sync(0xffffffffu, part, off);
    if (lane == 0) {
        float raw = part + bd2v;
        lg[j] = raw;
        d_logits[n * 64 + j] = raw;
    }
    __syncwarp();
}

// ---------------- select phase (512 threads, one block per batch row) ----------------
__device__ void select_phase(
    int n, const float* __restrict__ Wd1, const float* __restrict__ bd1,
    const float* __restrict__ Wd2, const float* __restrict__ bd2,
    const float* __restrict__ mask, const float* __restrict__ b2,
    const float* __restrict__ gc, const float* __restrict__ bc,
    int it, int P, int force0, int do_ln, SelS* sm)
{
    int tid = threadIdx.x, w = tid >> 5, lane = tid & 31;

    if (do_ln && d_flag[n] != 0)
        gate_ln(n, b2, gc, bc, sm);

    int mynext = (tid < 63) ? d_idx[n * 64 + tid + 1] : 0;

    if (!force0) {
        if (it > 0 && tid < P) sm->lg[tid] = d_logits[n * 64 + tid];
        __syncthreads();
        float bd2v = bd2[0];
        if (it == 0) {
            for (int j = w; j < P; j += 16)
                score_pair_g(n, j, lane, Wd1, Wd2, bd1, bd2v, sm->fs[w], sm->lg);
        } else {
            int pk = d_prevk[n];
            if (w < 2) {
                int j = pk - 1 + w;
                if (j >= 0 && j < P)
                    score_pair_g(n, j, lane, Wd1, Wd2, bd1, bd2v, sm->fs[w], sm->lg);
            }
        }
        __syncthreads();
    }

    // argmax with mask gating + first-index tie-break
    unsigned long long key = 0ull;
    if (!force0 && tid < P) {
        float mv = mask[n * 64 + it + 1 + tid];
        float v = (mv > 0.0f) ? sm->lg[tid] : -1e9f;
        unsigned u = __float_as_uint(v);
        u = (u & 0x80000000u) ? ~u : (u | 0x80000000u);
        key = ((unsigned long long)u << 32) | (unsigned)(63 - tid);
    }
#pragma unroll
    for (int off = 16; off > 0; off >>= 1) {
        unsigned long long o = __shfl_xor_sync(0xffffffffu, key, off);
        if (o > key) key = o;
    }
    if (lane == 0) sm->wmax[w] = key;
    __syncthreads();

    if (tid == 0) {
        unsigned long long best = sm->wmax[0];
#pragma unroll
        for (int ii = 1; ii < 16; ii++) if (sm->wmax[ii] > best) best = sm->wmax[ii];
        int k = force0 ? 0 : (63 - (int)(best & 0xFFFFFFFFu));
        float done = mask[n * 64 + it + 1];
        int sL = d_idx[n * 64 + k];
        int sR = d_idx[n * 64 + k + 1];
        int fl = (done > 0.0f) ? 1 : 0;
        if (!fl) { sL = d_idx[n * 64]; sR = d_idx[n * 64 + 1]; }
        sm->shk[0] = k; sm->shk[1] = sL; sm->shk[2] = sR; sm->shk[3] = fl;
        d_slotL[n] = sL; d_flag[n] = fl;
        d_prevk[n] = fl ? k : -1000;
    }
    __syncthreads();

    // compaction (idx + logits) + xcat gather
    float mylgnext = (tid < 63) ? d_logits[n * 64 + tid + 1] : 0.0f;
    __syncthreads();
    if (sm->shk[3]) {
        if (tid >= sm->shk[0] + 1 && tid <= P - 1) d_idx[n * 64 + tid] = mynext;
        if (tid >= sm->shk[0] + 1 && tid <= P - 2) d_logits[n * 64 + tid] = mylgnext;
    }

    int sL = sm->shk[1], sR = sm->shk[2];
    const float* lrow = d_cs + (size_t)(n * 64 + sL) * 512;
    const float* rrow = d_cs + (size_t)(n * 64 + sR) * 512;
    float* x = d_xcat + (size_t)n * 1024;
    x[tid] = lrow[tid];
    x[512 + tid] = rrow[tid];
}

// ---------------- the persistent kernel ----------------
__global__ __launch_bounds__(THREADS, 1) void persist_k(
    const float* __restrict__ input, const float* __restrict__ mask,
    const float* __restrict__ W_init, const float* __restrict__ b_init,
    const float* __restrict__ g_init, const float* __restrict__ beta_init,
    const float* __restrict__ W_d1, const float* __restrict__ b_d1,
    const float* __restrict__ W_d2, const float* __restrict__ b_d2,
    const float* __restrict__ W_c1, const float* __restrict__ b_c1,
    const float* __restrict__ W_c2, const float* __restrict__ b_c2,
    const float* __restrict__ g_c, const float* __restrict__ beta_c,
    float* __restrict__ out)
{
    __shared__ __align__(16) SmemU su;
    const int bid = blockIdx.x;
    const int tid = threadIdx.x;
    const int ntile = bid & 7;    // fc1/fc2 n-tile (256 cols); fc1 reduce group
    const int zidx  = bid >> 3;   // split-K index 0..15

    // ---- init GEMM: C0 = input @ W_init (8192x512 @ 512x512), 64m x 2n tiles ----
    gemm_tile(input, W_init, d_C0, 512, 512, (bid >> 1) * 128, (bid & 1) * 256, 0, 512, &su.g);
    gsync();

    // ---- init LayerNorm + idx init: rows of batch row `bid` (block-local for select) ----
    {
        float* sv = su.s.sv; float* red = su.s.red;
        for (int r = 0; r < 64; r++) {
            int row = bid * 64 + r;
            const float* src = d_C0 + (size_t)row * 512;
            sv[tid] = src[tid] + b_init[tid];
            __syncthreads();
            red[tid] = sv[tid]; __syncthreads();
            for (int off = 256; off > 0; off >>= 1) {
                if (tid < off) red[tid] += red[tid + off];
                __syncthreads();
            }
            float mean = red[0] * (1.0f / 512.0f);
            __syncthreads();
            float d0 = sv[tid] - mean;
            red[tid] = d0 * d0; __syncthreads();
            for (int off = 256; off > 0; off >>= 1) {
                if (tid < off) red[tid] += red[tid + off];
                __syncthreads();
            }
            float inv = 1.0f / sqrtf(red[0] * (1.0f / 512.0f) + 1e-5f);
            float* dst = d_cs + (size_t)row * 512;
            dst[tid] = (sv[tid] - mean) * inv * g_init[tid] + beta_init[tid];
            if (tid == 0) d_idx[row] = row & 63;
            __syncthreads();
        }
    }
    // no gsync needed: iteration-0 select of row `bid` reads only block-local data

    // ---- 63 merge iterations (dataflow-synchronized) ----
    for (int i = 0; i < 63; i++) {
        int P = 63 - i;

        // SELECT: every block handles batch row `bid` (needs all fc2 of iter i-1)
        wait_cnt(&c_fc2, 128u * (unsigned)i);
        select_phase(bid, W_d1, b_d1, W_d2, b_d2, mask, b_c2, g_c, beta_c,
                     i, P, (i == 62) ? 1 : 0, (i > 0) ? 1 : 0, &su.s);
        arrive_cnt(&c_sel);

        // FC1 partials: xcat(128x1024) @ W_c1(1024x2048); job (ntile, zidx), kc=64
        wait_cnt(&c_sel, 128u * (unsigned)(i + 1));
        gemm_tile(d_xcat, W_c1, d_part1 + (size_t)zidx * (NB * 2048),
                  2048, 1024, 0, ntile * 256, zidx * 64, 64, &su.g);

        // group barrier over the 16 blocks sharing this n-tile
        arrive_cnt(&c_grp[ntile]);
        wait_cnt(&c_grp[ntile], 16u * (unsigned)(i + 1));

        // cooperative reduce of h col-slice `ntile`: member zidx does rows [8z,8z+8)
        {
            int r = tid >> 6;                    // 0..7
            int c4g = ntile * 256 + ((tid & 63) << 2);
            size_t off = (size_t)(zidx * 8 + r) * 2048 + c4g;
            float4 s = *(const float4*)(d_part1 + off);
#pragma unroll
            for (int z2 = 1; z2 < SPLITK; z2++) {
                float4 p = *(const float4*)(d_part1 + (size_t)z2 * (NB * 2048) + off);
                s.x += p.x; s.y += p.y; s.z += p.z; s.w += p.w;
            }
            float4 bb = *(const float4*)(b_c1 + c4g);
            s.x = gelu_f(s.x + bb.x); s.y = gelu_f(s.y + bb.y);
            s.z = gelu_f(s.z + bb.z); s.w = gelu_f(s.w + bb.w);
            *(float4*)(d_h + off) = s;
        }
        arrive_cnt(&c_red[ntile]);

        // FC2 partials: h(128x2048) @ W_c2(2048x2048); needs h cols [z*128,+128)
        wait_cnt(&c_red[zidx >> 1], 16u * (unsigned)(i + 1));
        gemm_tile(d_h, W_c2, d_part2 + (size_t)zidx * (NB * 2048),
                  2048, 2048, 0, ntile * 256, zidx * 128, 128, &su.g);
        arrive_cnt(&c_fc2);
    }

    // ---- final gate+LN (iteration 62) + gather ----
    wait_cnt(&c_fc2, 128u * 63u);
    if (d_flag[bid] != 0)
        gate_ln(bid, b_c2, g_c, beta_c, &su.s);
    {
        int s0 = d_idx[bid * 64];
        const float* src = d_cs + (size_t)(bid * 64 + s0) * 512;
        out[(size_t)bid * 512 + tid] = src[tid];
    }

    // ---- reset dataflow counters for graph replay ----
    gsync();
    if (bid == 0 && tid == 0) {
        c_sel = 0u; c_fc2 = 0u;
#pragma unroll
        for (int g = 0; g < 8; g++) { c_grp[g] = 0u; c_red[g] = 0u; }
    }
}

// ---------------- host launcher (graph-capturable: one kernel launch) ----------------
extern "C" void kernel_launch(void* const* d_in, const int* in_sizes, int n_in,
                              void* d_out, int out_size)
{
    const float* input     = (const float*)d_in[0];
    const float* mask      = (const float*)d_in[1];
    const float* W_init    = (const float*)d_in[2];
    const float* b_init    = (const float*)d_in[3];
    const float* g_init    = (const float*)d_in[4];
    const float* beta_init = (const float*)d_in[5];
    const float* W_d1      = (const float*)d_in[6];
    const float* b_d1      = (const float*)d_in[7];
    const float* W_d2      = (const float*)d_in[8];
    const float* b_d2      = (const float*)d_in[9];
    const float* W_c1      = (const float*)d_in[10];
    const float* b_c1      = (const float*)d_in[11];
    const float* W_c2      = (const float*)d_in[12];
    const float* b_c2      = (const float*)d_in[13];
    const float* g_c       = (const float*)d_in[14];
    const float* beta_c    = (const float*)d_in[15];

    persist_k<<<GRID, THREADS>>>(input, mask, W_init, b_init, g_init, beta_init,
                                 W_d1, b_d1, W_d2, b_d2, W_c1, b_c1, W_c2, b_c2,
                                 g_c, beta_c, (float*)d_out);
}

// round 16
// speedup vs baseline: 1.0387x; 1.0387x over previous
#include <cuda_runtime.h>
#include <math.h>

// Problem constants
#define NB 128       // batch
#define GRID 128
#define THREADS 512
#define SPLITK 16    // split-K for fc1 (kc=64) and fc2 (kc=128)

// ---------------- device scratch (no allocations allowed) ----------------
__device__ float d_cs[NB * 64 * 512];          // chart states, slot-addressed
__device__ float d_C0[NB * 64 * 512];          // init GEMM output
__device__ float d_part1[SPLITK * NB * 2048];  // fc1 split-K partials
__device__ float d_part2[SPLITK * NB * 2048];  // fc2 split-K partials
__device__ float d_h[NB * 2048];               // fc1 activations
__device__ float d_xcat[NB * 1024];            // [l, r] concat for selected pairs
__device__ float d_logits[NB * 64];            // cached raw pair logits
__device__ int   d_idx[NB * 64];               // active slot list per row
__device__ int   d_slotL[NB];
__device__ int   d_flag[NB];
__device__ int   d_prevk[NB];
// dataflow counters (generation-indexed, monotone within a launch)
__device__ unsigned int c_sel = 0;             // select completions (128/iter)
__device__ unsigned int c_grp[8] = {};         // fc1 group arrivals (16/iter each)
__device__ unsigned int c_red[8] = {};         // h-slice reduce completions
__device__ unsigned int c_fc2 = 0;             // fc2 job completions (128/iter)
__device__ unsigned int g_cnt = 0;             // classic grid barrier
__device__ unsigned int g_gen = 0;

struct GemmS { float As[2][16][128]; float Bs[2][16][256]; };   // 48 KB
struct SelS  { float fs[16][128]; float sv[512]; float red[512];
               float lg[64]; unsigned long long wmax[16]; int shk[4]; };
union SmemU  { GemmS g; SelS s; };

__device__ __forceinline__ float gelu_f(float x) {
    float x3 = x * x * x;
    return 0.5f * x * (1.0f + tanhf(0.7978845608028654f * (x + 0.044715f * x3)));
}
__device__ __forceinline__ float sigm_f(float x) {
    return 1.0f / (1.0f + expf(-x));
}

// ---------------- sync primitives ----------------
__device__ __forceinline__ void gsync() {
    __syncthreads();
    if (threadIdx.x == 0) {
        __threadfence();
        unsigned int g = *(volatile unsigned int*)&g_gen;
        if (atomicAdd(&g_cnt, 1u) == GRID - 1u) {
            g_cnt = 0u;
            __threadfence();
            *(volatile unsigned int*)&g_gen = g + 1u;
        } else {
            while (*(volatile unsigned int*)&g_gen == g) __nanosleep(32);
        }
        __threadfence();
    }
    __syncthreads();
}
__device__ __forceinline__ void arrive_cnt(unsigned int* c) {
    __threadfence();
    __syncthreads();
    if (threadIdx.x == 0) atomicAdd(c, 1u);
}
__device__ __forceinline__ void wait_cnt(unsigned int* c, unsigned int tgt) {
    if (threadIdx.x == 0) {
        while (*(volatile unsigned int*)c < tgt) __nanosleep(64);
        __threadfence();
    }
    __syncthreads();
}

// ---------------- 128x256 GEMM tile, 512 threads, double-buffered f32x2 ----------------
// A: (.)xK row-major, B: KxN row-major. C[m0:m0+128, n0:n0+256] over K-range
// [k0,k0+kc) into Co (leading dim N). Per-output accumulation order identical
// to the previous 128x128 version -> bit-identical results.
__device__ __forceinline__ void gemm_tile(
    const float* __restrict__ A, const float* __restrict__ B, float* __restrict__ Co,
    int N, int K, int m0, int n0, int k0, int kc, GemmS* sm)
{
    const int tid = threadIdx.x;
    const int tx = tid & 31;        // 32 col-groups of 8
    const int ty = tid >> 5;        // 16 row-groups of 8
    const int nk = kc >> 4;

    unsigned long long accp[8][4];
#pragma unroll
    for (int i = 0; i < 8; i++)
#pragma unroll
        for (int j = 0; j < 4; j++) accp[i][j] = 0ull;

    const int arow = tid >> 2;           // 0..127
    const int ac4  = (tid & 3) << 2;     // 0,4,8,12
    const int brow = tid >> 6;           // 0..7
    const int bc4  = (tid & 63) << 2;    // 0..252

    const float* Ap = A + (size_t)(m0 + arow) * K + k0 + ac4;
    const float* Bp = B + (size_t)(k0 + brow) * N + n0 + bc4;

    float4 ta  = *(const float4*)(Ap);
    float4 tb0 = *(const float4*)(Bp);
    float4 tb1 = *(const float4*)(Bp + (size_t)8 * N);
    sm->As[0][ac4 + 0][arow] = ta.x; sm->As[0][ac4 + 1][arow] = ta.y;
    sm->As[0][ac4 + 2][arow] = ta.z; sm->As[0][ac4 + 3][arow] = ta.w;
    *(float4*)&sm->Bs[0][brow][bc4]     = tb0;
    *(float4*)&sm->Bs[0][brow + 8][bc4] = tb1;
    __syncthreads();

    int buf = 0;
    for (int t = 0; t < nk; t++) {
        if (t + 1 < nk) {
            const float* Apn = Ap + (t + 1) * 16;
            const float* Bpn = Bp + (size_t)(t + 1) * 16 * N;
            ta  = *(const float4*)(Apn);
            tb0 = *(const float4*)(Bpn);
            tb1 = *(const float4*)(Bpn + (size_t)8 * N);
        }
#pragma unroll
        for (int kk = 0; kk < 16; kk++) {
            float av[8];
            unsigned long long avp[8], bvp[4];
            *(float4*)(av)     = *(const float4*)&sm->As[buf][kk][ty * 8];
            *(float4*)(av + 4) = *(const float4*)&sm->As[buf][kk][ty * 8 + 4];
            *(ulonglong2*)(bvp + 0) = *(const ulonglong2*)&sm->Bs[buf][kk][tx * 8 + 0];
            *(ulonglong2*)(bvp + 2) = *(const ulonglong2*)&sm->Bs[buf][kk][tx * 8 + 4];
#pragma unroll
            for (int i = 0; i < 8; i++)
                asm("mov.b64 %0, {%1, %1};" : "=l"(avp[i]) : "f"(av[i]));
#pragma unroll
            for (int i = 0; i < 8; i++)
#pragma unroll
                for (int j = 0; j < 4; j++)
                    asm("fma.rn.f32x2 %0, %1, %2, %0;"
                        : "+l"(accp[i][j]) : "l"(avp[i]), "l"(bvp[j]));
        }
        if (t + 1 < nk) {
            int nb = buf ^ 1;
            sm->As[nb][ac4 + 0][arow] = ta.x; sm->As[nb][ac4 + 1][arow] = ta.y;
            sm->As[nb][ac4 + 2][arow] = ta.z; sm->As[nb][ac4 + 3][arow] = ta.w;
            *(float4*)&sm->Bs[nb][brow][bc4]     = tb0;
            *(float4*)&sm->Bs[nb][brow + 8][bc4] = tb1;
            __syncthreads();
            buf = nb;
        }
    }

#pragma unroll
    for (int i = 0; i < 8; i++) {
        ulonglong2 v0 = make_ulonglong2(accp[i][0], accp[i][1]);
        ulonglong2 v1 = make_ulonglong2(accp[i][2], accp[i][3]);
        *(ulonglong2*)(Co + (size_t)(m0 + ty * 8 + i) * N + n0 + tx * 8)     = v0;
        *(ulonglong2*)(Co + (size_t)(m0 + ty * 8 + i) * N + n0 + tx * 8 + 4) = v1;
    }
}

// ---------------- fc2 split-K reduce + gates + LayerNorm into cs[sL] ----------------
__device__ void gate_ln(int n, const float* __restrict__ b2, const float* __restrict__ g,
                        const float* __restrict__ beta, SelS* sm)
{
    int tid = threadIdx.x;    // 512: one d per thread
    float* sv = sm->sv; float* red = sm->red;
    const float* base = d_part2 + (size_t)n * 2048;
    {
        int d = tid;
        float c0 = 0.f, c1 = 0.f, c2 = 0.f, c3 = 0.f;
#pragma unroll
        for (int z = 0; z < SPLITK; z++) {
            const float* pp = base + (size_t)z * (NB * 2048);
            c0 += pp[d]; c1 += pp[512 + d]; c2 += pp[1024 + d]; c3 += pp[1536 + d];
        }
        c0 += b2[d]; c1 += b2[512 + d]; c2 += b2[1024 + d]; c3 += b2[1536 + d];
        float l = d_xcat[(size_t)n * 1024 + d];
        float r = d_xcat[(size_t)n * 1024 + 512 + d];
        sv[d] = sigm_f(c0) * l + sigm_f(c1) * r + sigm_f(c2) * c3;
    }
    __syncthreads();
    red[tid] = sv[tid]; __syncthreads();
    for (int off = 256; off > 0; off >>= 1) {
        if (tid < off) red[tid] += red[tid + off];
        __syncthreads();
    }
    float mean = red[0] * (1.0f / 512.0f);
    __syncthreads();
    float d0 = sv[tid] - mean;
    red[tid] = d0 * d0; __syncthreads();
    for (int off = 256; off > 0; off >>= 1) {
        if (tid < off) red[tid] += red[tid + off];
        __syncthreads();
    }
    float inv = 1.0f / sqrtf(red[0] * (1.0f / 512.0f) + 1e-5f);
    float* dst = d_cs + (size_t)(n * 64 + d_slotL[n]) * 512;
    dst[tid] = (sv[tid] - mean) * inv * g[tid] + beta[tid];
    __syncthreads();
}

// ---------------- pair scorer (one warp per pair; weights from L2) ----------------
__device__ __forceinline__ void score_pair_g(
    int n, int j, int lane,
    const float* __restrict__ Wd1, const float* __restrict__ Wd2,
    const float* __restrict__ bd1, float bd2v, float* fsrow, float* lg)
{
    int a  = d_idx[n * 64 + j];
    int bs = d_idx[n * 64 + j + 1];
    const float* lrow = d_cs + (size_t)(n * 64 + a) * 512;
    const float* rrow = d_cs + (size_t)(n * 64 + bs) * 512;
    for (int t = lane; t < 128; t += 32)
        fsrow[t] = (t < 64) ? lrow[t] : rrow[t - 64];
    __syncwarp();
    float acc0 = 0.0f, acc1 = 0.0f;
#pragma unroll 8
    for (int k = 0; k < 128; k++) {
        float f = fsrow[k];
        acc0 = fmaf(f, Wd1[k * 64 + lane], acc0);
        acc1 = fmaf(f, Wd1[k * 64 + lane + 32], acc1);
    }
    float h0 = gelu_f(acc0 + bd1[lane]);
    float h1 = gelu_f(acc1 + bd1[lane + 32]);
    float part = h0 * Wd2[lane] + h1 * Wd2[lane + 32];
#pragma unroll
    for (int off = 16; off > 0; off >>= 1)
        part += __shfl_xor_sync(0xffffffffu, part, off);
    if (lane == 0) {
        float raw = part + bd2v;
        lg[j] = raw;
        d_logits[n * 64 + j] = raw;
    }
    __syncwarp();
}

// ---------------- select phase (512 threads, one block per batch row) ----------------
__device__ void select_phase(
    int n, const float* __restrict__ Wd1, const float* __restrict__ bd1,
    const float* __restrict__ Wd2, const float* __restrict__ bd2,
    const float* __restrict__ mask, const float* __restrict__ b2,
    const float* __restrict__ gc, const float* __restrict__ bc,
    int it, int P, int force0, int do_ln, SelS* sm)
{
    int tid = threadIdx.x, w = tid >> 5, lane = tid & 31;

    if (do_ln && d_flag[n] != 0)
        gate_ln(n, b2, gc, bc, sm);

    int mynext = (tid < 63) ? d_idx[n * 64 + tid + 1] : 0;

    if (!force0) {
        if (it > 0 && tid < P) sm->lg[tid] = d_logits[n * 64 + tid];
        __syncthreads();
        float bd2v = bd2[0];
        if (it == 0) {
            for (int j = w; j < P; j += 16)
                score_pair_g(n, j, lane, Wd1, Wd2, bd1, bd2v, sm->fs[w], sm->lg);
        } else {
            int pk = d_prevk[n];
            if (w < 2) {
                int j = pk - 1 + w;
                if (j >= 0 && j < P)
                    score_pair_g(n, j, lane, Wd1, Wd2, bd1, bd2v, sm->fs[w], sm->lg);
            }
        }
        __syncthreads();
    }

    // argmax with mask gating + first-index tie-break
    unsigned long long key = 0ull;
    if (!force0 && tid < P) {
        float mv = mask[n * 64 + it + 1 + tid];
        float v = (mv > 0.0f) ? sm->lg[tid] : -1e9f;
        unsigned u = __float_as_uint(v);
        u = (u & 0x80000000u) ? ~u : (u | 0x80000000u);
        key = ((unsigned long long)u << 32) | (unsigned)(63 - tid);
    }
#pragma unroll
    for (int off = 16; off > 0; off >>= 1) {
        unsigned long long o = __shfl_xor_sync(0xffffffffu, key, off);
        if (o > key) key = o;
    }
    if (lane == 0) sm->wmax[w] = key;
    __syncthreads();

    if (tid == 0) {
        unsigned long long best = sm->wmax[0];
#pragma unroll
        for (int ii = 1; ii < 16; ii++) if (sm->wmax[ii] > best) best = sm->wmax[ii];
        int k = force0 ? 0 : (63 - (int)(best & 0xFFFFFFFFu));
        float done = mask[n * 64 + it + 1];
        int sL = d_idx[n * 64 + k];
        int sR = d_idx[n * 64 + k + 1];
        int fl = (done > 0.0f) ? 1 : 0;
        if (!fl) { sL = d_idx[n * 64]; sR = d_idx[n * 64 + 1]; }
        sm->shk[0] = k; sm->shk[1] = sL; sm->shk[2] = sR; sm->shk[3] = fl;
        d_slotL[n] = sL; d_flag[n] = fl;
        d_prevk[n] = fl ? k : -1000;
    }
    __syncthreads();

    // compaction (idx + logits) + xcat gather
    float mylgnext = (tid < 63) ? d_logits[n * 64 + tid + 1] : 0.0f;
    __syncthreads();
    if (sm->shk[3]) {
        if (tid >= sm->shk[0] + 1 && tid <= P - 1) d_idx[n * 64 + tid] = mynext;
        if (tid >= sm->shk[0] + 1 && tid <= P - 2) d_logits[n * 64 + tid] = mylgnext;
    }

    int sL = sm->shk[1], sR = sm->shk[2];
    const float* lrow = d_cs + (size_t)(n * 64 + sL) * 512;
    const float* rrow = d_cs + (size_t)(n * 64 + sR) * 512;
    float* x = d_xcat + (size_t)n * 1024;
    x[tid] = lrow[tid];
    x[512 + tid] = rrow[tid];
}

// ---------------- the persistent kernel ----------------
__global__ __launch_bounds__(THREADS, 1) void persist_k(
    const float* __restrict__ input, const float* __restrict__ mask,
    const float* __restrict__ W_init, const float* __restrict__ b_init,
    const float* __restrict__ g_init, const float* __restrict__ beta_init,
    const float* __restrict__ W_d1, const float* __restrict__ b_d1,
    const float* __restrict__ W_d2, const float* __restrict__ b_d2,
    const float* __restrict__ W_c1, const float* __restrict__ b_c1,
    const float* __restrict__ W_c2, const float* __restrict__ b_c2,
    const float* __restrict__ g_c, const float* __restrict__ beta_c,
    float* __restrict__ out)
{
    __shared__ __align__(16) SmemU su;
    const int bid = blockIdx.x;
    const int tid = threadIdx.x;
    const int ntile = bid & 7;    // fc1/fc2 n-tile (256 cols); fc1 reduce group
    const int zidx  = bid >> 3;   // split-K index 0..15

    // ---- init GEMM: C0 = input @ W_init (8192x512 @ 512x512), 64m x 2n tiles ----
    gemm_tile(input, W_init, d_C0, 512, 512, (bid >> 1) * 128, (bid & 1) * 256, 0, 512, &su.g);
    gsync();

    // ---- init LayerNorm + idx init: rows of batch row `bid` (block-local for select) ----
    {
        float* sv = su.s.sv; float* red = su.s.red;
        for (int r = 0; r < 64; r++) {
            int row = bid * 64 + r;
            const float* src = d_C0 + (size_t)row * 512;
            sv[tid] = src[tid] + b_init[tid];
            __syncthreads();
            red[tid] = sv[tid]; __syncthreads();
            for (int off = 256; off > 0; off >>= 1) {
                if (tid < off) red[tid] += red[tid + off];
                __syncthreads();
            }
            float mean = red[0] * (1.0f / 512.0f);
            __syncthreads();
            float d0 = sv[tid] - mean;
            red[tid] = d0 * d0; __syncthreads();
            for (int off = 256; off > 0; off >>= 1) {
                if (tid < off) red[tid] += red[tid + off];
                __syncthreads();
            }
            float inv = 1.0f / sqrtf(red[0] * (1.0f / 512.0f) + 1e-5f);
            float* dst = d_cs + (size_t)row * 512;
            dst[tid] = (sv[tid] - mean) * inv * g_init[tid] + beta_init[tid];
            if (tid == 0) d_idx[row] = row & 63;
            __syncthreads();
        }
    }
    // no gsync needed: iteration-0 select of row `bid` reads only block-local data

    // ---- 63 merge iterations (dataflow-synchronized) ----
    for (int i = 0; i < 63; i++) {
        int P = 63 - i;

        // SELECT: every block handles batch row `bid` (needs all fc2 of iter i-1)
        wait_cnt(&c_fc2, 128u * (unsigned)i);
        select_phase(bid, W_d1, b_d1, W_d2, b_d2, mask, b_c2, g_c, beta_c,
                     i, P, (i == 62) ? 1 : 0, (i > 0) ? 1 : 0, &su.s);
        arrive_cnt(&c_sel);

        // FC1 partials: xcat(128x1024) @ W_c1(1024x2048); job (ntile, zidx), kc=64
        wait_cnt(&c_sel, 128u * (unsigned)(i + 1));
        gemm_tile(d_xcat, W_c1, d_part1 + (size_t)zidx * (NB * 2048),
                  2048, 1024, 0, ntile * 256, zidx * 64, 64, &su.g);

        // group barrier over the 16 blocks sharing this n-tile
        arrive_cnt(&c_grp[ntile]);
        wait_cnt(&c_grp[ntile], 16u * (unsigned)(i + 1));

        // cooperative reduce of h col-slice `ntile`: member zidx does rows [8z,8z+8)
        {
            int r = tid >> 6;                    // 0..7
            int c4g = ntile * 256 + ((tid & 63) << 2);
            size_t off = (size_t)(zidx * 8 + r) * 2048 + c4g;
            float4 s = *(const float4*)(d_part1 + off);
#pragma unroll
            for (int z2 = 1; z2 < SPLITK; z2++) {
                float4 p = *(const float4*)(d_part1 + (size_t)z2 * (NB * 2048) + off);
                s.x += p.x; s.y += p.y; s.z += p.z; s.w += p.w;
            }
            float4 bb = *(const float4*)(b_c1 + c4g);
            s.x = gelu_f(s.x + bb.x); s.y = gelu_f(s.y + bb.y);
            s.z = gelu_f(s.z + bb.z); s.w = gelu_f(s.w + bb.w);
            *(float4*)(d_h + off) = s;
        }
        arrive_cnt(&c_red[ntile]);

        // FC2 partials: h(128x2048) @ W_c2(2048x2048); needs h cols [z*128,+128)
        wait_cnt(&c_red[zidx >> 1], 16u * (unsigned)(i + 1));
        gemm_tile(d_h, W_c2, d_part2 + (size_t)zidx * (NB * 2048),
                  2048, 2048, 0, ntile * 256, zidx * 128, 128, &su.g);
        arrive_cnt(&c_fc2);
    }

    // ---- final gate+LN (iteration 62) + gather ----
    wait_cnt(&c_fc2, 128u * 63u);
    if (d_flag[bid] != 0)
        gate_ln(bid, b_c2, g_c, beta_c, &su.s);
    {
        int s0 = d_idx[bid * 64];
        const float* src = d_cs + (size_t)(bid * 64 + s0) * 512;
        out[(size_t)bid * 512 + tid] = src[tid];
    }

    // ---- reset dataflow counters for graph replay ----
    gsync();
    if (bid == 0 && tid == 0) {
        c_sel = 0u; c_fc2 = 0u;
#pragma unroll
        for (int g = 0; g < 8; g++) { c_grp[g] = 0u; c_red[g] = 0u; }
    }
}

// ---------------- host launcher (graph-capturable: one kernel launch) ----------------
extern "C" void kernel_launch(void* const* d_in, const int* in_sizes, int n_in,
                              void* d_out, int out_size)
{
    const float* input     = (const float*)d_in[0];
    const float* mask      = (const float*)d_in[1];
    const float* W_init    = (const float*)d_in[2];
    const float* b_init    = (const float*)d_in[3];
    const float* g_init    = (const float*)d_in[4];
    const float* beta_init = (const float*)d_in[5];
    const float* W_d1      = (const float*)d_in[6];
    const float* b_d1      = (const float*)d_in[7];
    const float* W_d2      = (const float*)d_in[8];
    const float* b_d2      = (const float*)d_in[9];
    const float* W_c1      = (const float*)d_in[10];
    const float* b_c1      = (const float*)d_in[11];
    const float* W_c2      = (const float*)d_in[12];
    const float* b_c2      = (const float*)d_in[13];
    const float* g_c       = (const float*)d_in[14];
    const float* beta_c    = (const float*)d_in[15];

    persist_k<<<GRID, THREADS>>>(input, mask, W_init, b_init, g_init, beta_init,
                                 W_d1, b_d1, W_d2, b_d2, W_c1, b_c1, W_c2, b_c2,
                                 g_c, beta_c, (float*)d_out);
}